// round 2
// baseline (speedup 1.0000x reference)
#include <cuda_runtime.h>

#define NB 8
#define LQ 256
#define LK 256
#define HH 256
#define DV 256
#define MASK_VALUE -1000000.0f

typedef unsigned long long u64;

// Scratch (allocation-free rule: device globals)
__device__ float g_Qp[NB * LQ * HH];
__device__ float g_Kp[NB * LK * HH];
__device__ float g_S[NB * LQ * LK];

__device__ __forceinline__ float tanh_fast(float x) {
    float y;
    asm("tanh.approx.f32 %0, %1;" : "=f"(y) : "f"(x));
    return y;
}

__device__ __forceinline__ u64 pack2(float lo, float hi) {
    u64 r;
    asm("mov.b64 %0, {%1, %2};" : "=l"(r) : "f"(lo), "f"(hi));
    return r;
}
__device__ __forceinline__ u64 dup2(float x) { return pack2(x, x); }

__device__ __forceinline__ void fma2(u64& d, u64 a, u64 b) {
    asm("fma.rn.f32x2 %0, %1, %2, %0;" : "+l"(d) : "l"(a), "l"(b));
}
__device__ __forceinline__ float2 unpack2(u64 v) {
    float2 f;
    asm("mov.b64 {%0, %1}, %2;" : "=f"(f.x), "=f"(f.y) : "l"(v));
    return f;
}

// ---------------------------------------------------------------------------
// Projection NT GEMM: C[m][n] = sum_k X[m][k] * W[n][k]
// M = 2048 (B*L rows), N = 256, K = 256.
// Tile 128(m) x 64(n), kc = 32, 256 threads, thread computes 8x4 via FFMA2.
// blockIdx.z: 0 -> queries@W_q^T -> g_Qp, 1 -> keyes@W_k^T -> g_Kp
// ---------------------------------------------------------------------------
#define PSA 132   // 128 + 4 row stride for As (floats)
#define PSB 68    // 64 + 4 row stride for Bs (floats)

__global__ void __launch_bounds__(256) proj_kernel(
    const float* __restrict__ Xq, const float* __restrict__ Wq,
    const float* __restrict__ Xk, const float* __restrict__ Wk) {
    const float* X;
    const float* W;
    float* C;
    if (blockIdx.z == 0) { X = Xq; W = Wq; C = g_Qp; }
    else                 { X = Xk; W = Wk; C = g_Kp; }

    __shared__ float As[32 * PSA];  // [k][m]
    __shared__ float Bs[32 * PSB];  // [k][n]

    const int tid = threadIdx.x;
    const int tx = tid & 15;   // n: tx*4
    const int ty = tid >> 4;   // m: ty*8
    const int m0 = blockIdx.y * 128;
    const int n0 = blockIdx.x * 64;

    u64 acc[8][2];
    #pragma unroll
    for (int i = 0; i < 8; i++) { acc[i][0] = 0ull; acc[i][1] = 0ull; }

    float4 ra[4], rb[2];

    // prefetch k0 = 0
    #pragma unroll
    for (int j = 0; j < 4; j++) {
        int idx = tid + j * 256;                 // 0..1023
        int r = idx >> 3, c4 = idx & 7;          // r: 0..127
        ra[j] = *(const float4*)&X[(m0 + r) * 256 + c4 * 4];
    }
    #pragma unroll
    for (int j = 0; j < 2; j++) {
        int idx = tid + j * 256;                 // 0..511
        int r = idx >> 3, c4 = idx & 7;          // r: 0..63
        rb[j] = *(const float4*)&W[(n0 + r) * 256 + c4 * 4];
    }

    for (int k0 = 0; k0 < 256; k0 += 32) {
        // store prefetched regs (transposed) into smem
        #pragma unroll
        for (int j = 0; j < 4; j++) {
            int idx = tid + j * 256;
            int r = idx >> 3, c = (idx & 7) * 4;
            As[(c + 0) * PSA + r] = ra[j].x;
            As[(c + 1) * PSA + r] = ra[j].y;
            As[(c + 2) * PSA + r] = ra[j].z;
            As[(c + 3) * PSA + r] = ra[j].w;
        }
        #pragma unroll
        for (int j = 0; j < 2; j++) {
            int idx = tid + j * 256;
            int r = idx >> 3, c = (idx & 7) * 4;
            Bs[(c + 0) * PSB + r] = rb[j].x;
            Bs[(c + 1) * PSB + r] = rb[j].y;
            Bs[(c + 2) * PSB + r] = rb[j].z;
            Bs[(c + 3) * PSB + r] = rb[j].w;
        }
        __syncthreads();

        // prefetch next k tile (overlaps mainloop)
        if (k0 < 224) {
            int kn = k0 + 32;
            #pragma unroll
            for (int j = 0; j < 4; j++) {
                int idx = tid + j * 256;
                int r = idx >> 3, c4 = idx & 7;
                ra[j] = *(const float4*)&X[(m0 + r) * 256 + kn + c4 * 4];
            }
            #pragma unroll
            for (int j = 0; j < 2; j++) {
                int idx = tid + j * 256;
                int r = idx >> 3, c4 = idx & 7;
                rb[j] = *(const float4*)&W[(n0 + r) * 256 + kn + c4 * 4];
            }
        }

        #pragma unroll
        for (int kk = 0; kk < 32; kk++) {
            float4 b = *(const float4*)&Bs[kk * PSB + tx * 4];
            u64 b0 = pack2(b.x, b.y);
            u64 b1 = pack2(b.z, b.w);
            float4 a0 = *(const float4*)&As[kk * PSA + ty * 8];
            float4 a1 = *(const float4*)&As[kk * PSA + ty * 8 + 4];
            u64 d0 = dup2(a0.x), d1 = dup2(a0.y), d2 = dup2(a0.z), d3 = dup2(a0.w);
            u64 d4 = dup2(a1.x), d5 = dup2(a1.y), d6 = dup2(a1.z), d7 = dup2(a1.w);
            fma2(acc[0][0], d0, b0); fma2(acc[0][1], d0, b1);
            fma2(acc[1][0], d1, b0); fma2(acc[1][1], d1, b1);
            fma2(acc[2][0], d2, b0); fma2(acc[2][1], d2, b1);
            fma2(acc[3][0], d3, b0); fma2(acc[3][1], d3, b1);
            fma2(acc[4][0], d4, b0); fma2(acc[4][1], d4, b1);
            fma2(acc[5][0], d5, b0); fma2(acc[5][1], d5, b1);
            fma2(acc[6][0], d6, b0); fma2(acc[6][1], d6, b1);
            fma2(acc[7][0], d7, b0); fma2(acc[7][1], d7, b1);
        }
        __syncthreads();
    }

    #pragma unroll
    for (int i = 0; i < 8; i++) {
        float2 p0 = unpack2(acc[i][0]);
        float2 p1 = unpack2(acc[i][1]);
        *(float4*)&C[(m0 + ty * 8 + i) * 256 + n0 + tx * 4] =
            make_float4(p0.x, p0.y, p1.x, p1.y);
    }
}

// ---------------------------------------------------------------------------
// Scores: S[b][q][k] = sum_h Wv[h] * tanh(Qp[b][q][h] + Kp[b][k][h]),
// masked to MASK_VALUE where k >= valid_len[b]. Fully-masked 32x32 tiles skip
// all compute. MUFU-bound by design.
// ---------------------------------------------------------------------------
__global__ void scores_kernel(const float* __restrict__ Wv,
                              const int* __restrict__ vlens) {
    const int b = blockIdx.z;
    const int q0 = blockIdx.y * 32;
    const int k0 = blockIdx.x * 32;
    const int tid = threadIdx.x;
    const int tx = tid & 15;
    const int ty = tid >> 4;
    const int vl = vlens[b];
    float* S = g_S + b * LQ * LK;

    if (k0 >= vl) {
        const float2 mv = make_float2(MASK_VALUE, MASK_VALUE);
        #pragma unroll
        for (int i = 0; i < 2; i++)
            *(float2*)&S[(q0 + ty * 2 + i) * LK + k0 + tx * 2] = mv;
        return;
    }

    __shared__ float Qs[64][34];
    __shared__ float Ks[64][34];
    __shared__ float sWv[256];

    sWv[tid] = Wv[tid];

    const float* Qb = g_Qp + (b * LQ + q0) * HH;
    const float* Kb = g_Kp + (b * LK + k0) * HH;

    float a00 = 0.f, a01 = 0.f, a10 = 0.f, a11 = 0.f;

    for (int h0 = 0; h0 < HH; h0 += 64) {
        #pragma unroll
        for (int idx = tid; idx < 32 * 64; idx += 256) {
            int r = idx >> 6;
            int h = idx & 63;
            Qs[h][r] = Qb[r * HH + h0 + h];
            Ks[h][r] = Kb[r * HH + h0 + h];
        }
        __syncthreads();
        #pragma unroll 8
        for (int h = 0; h < 64; h++) {
            float2 qv = *(const float2*)&Qs[h][ty * 2];
            float2 kv = *(const float2*)&Ks[h][tx * 2];
            float wv = sWv[h0 + h];
            a00 += wv * tanh_fast(qv.x + kv.x);
            a01 += wv * tanh_fast(qv.x + kv.y);
            a10 += wv * tanh_fast(qv.y + kv.x);
            a11 += wv * tanh_fast(qv.y + kv.y);
        }
        __syncthreads();
    }

    const int kA = k0 + tx * 2;
    const int kB = kA + 1;
    const int qA = q0 + ty * 2;
    const int qB = qA + 1;
    S[qA * LK + kA] = (kA < vl) ? a00 : MASK_VALUE;
    S[qA * LK + kB] = (kB < vl) ? a01 : MASK_VALUE;
    S[qB * LK + kA] = (kA < vl) ? a10 : MASK_VALUE;
    S[qB * LK + kB] = (kB < vl) ? a11 : MASK_VALUE;
}

// ---------------------------------------------------------------------------
// Softmax over axis=1 (QUERY axis) per (b, k) column — reference quirk.
// ---------------------------------------------------------------------------
__global__ void softmax_kernel() {
    const int b = blockIdx.y;
    const int tx = threadIdx.x & 31;
    const int ty = threadIdx.x >> 5;  // 0..7
    const int k = blockIdx.x * 32 + tx;
    float* S = g_S + b * LQ * LK;

    float vals[32];
    float m = -3.4e38f;
    #pragma unroll
    for (int i = 0; i < 32; i++) {
        vals[i] = S[(i * 8 + ty) * LK + k];
        m = fmaxf(m, vals[i]);
    }

    __shared__ float red[8][33];
    red[ty][tx] = m;
    __syncthreads();
    float M = red[0][tx];
    #pragma unroll
    for (int t = 1; t < 8; t++) M = fmaxf(M, red[t][tx]);
    __syncthreads();

    float s = 0.f;
    #pragma unroll
    for (int i = 0; i < 32; i++) {
        vals[i] = __expf(vals[i] - M);
        s += vals[i];
    }
    red[ty][tx] = s;
    __syncthreads();
    float SUM = 0.f;
    #pragma unroll
    for (int t = 0; t < 8; t++) SUM += red[t][tx];

    const float inv = 1.0f / SUM;
    #pragma unroll
    for (int i = 0; i < 32; i++)
        S[(i * 8 + ty) * LK + k] = vals[i] * inv;
}

// ---------------------------------------------------------------------------
// Output NN GEMM: out[b][q][d] = sum_k Attn[b][q][k] * V[b][k][d]
// Tile 64(q) x 64(d), kc = 32, 256 threads, thread computes 4x4 via FFMA2.
// ---------------------------------------------------------------------------
__global__ void __launch_bounds__(256) out_kernel(
    const float* __restrict__ Vv, float* __restrict__ out) {
    const int b = blockIdx.z;
    const int q0 = blockIdx.y * 64;
    const int d0 = blockIdx.x * 64;
    const int tid = threadIdx.x;
    const int tx = tid & 15;   // d: tx*4
    const int ty = tid >> 4;   // q: ty*4

    const float* A = g_S + b * LQ * LK;
    const float* V = Vv + b * LK * DV;

    __shared__ float As[32 * PSB];  // [k][q], stride 68
    __shared__ float Vs[32 * PSB];  // [k][d], stride 68

    u64 acc[4][2];
    #pragma unroll
    for (int i = 0; i < 4; i++) { acc[i][0] = 0ull; acc[i][1] = 0ull; }

    float4 raA[2], raV[2];

    // prefetch k0 = 0
    #pragma unroll
    for (int j = 0; j < 2; j++) {
        int idx = tid + j * 256;                 // A tile 64x32 -> 512 float4
        int r = idx >> 3, c4 = idx & 7;
        raA[j] = *(const float4*)&A[(q0 + r) * LK + c4 * 4];
    }
    #pragma unroll
    for (int j = 0; j < 2; j++) {
        int idx = tid + j * 256;                 // V tile 32x64 -> 512 float4
        int r = idx >> 4, c4 = idx & 15;
        raV[j] = *(const float4*)&V[r * DV + d0 + c4 * 4];
    }

    for (int k0 = 0; k0 < LK; k0 += 32) {
        #pragma unroll
        for (int j = 0; j < 2; j++) {
            int idx = tid + j * 256;
            int r = idx >> 3, c = (idx & 7) * 4;   // transpose A -> [k][q]
            As[(c + 0) * PSB + r] = raA[j].x;
            As[(c + 1) * PSB + r] = raA[j].y;
            As[(c + 2) * PSB + r] = raA[j].z;
            As[(c + 3) * PSB + r] = raA[j].w;
        }
        #pragma unroll
        for (int j = 0; j < 2; j++) {
            int idx = tid + j * 256;
            int r = idx >> 4, c4 = idx & 15;       // V direct [k][d]
            *(float4*)&Vs[r * PSB + c4 * 4] = raV[j];
        }
        __syncthreads();

        if (k0 < LK - 32) {
            int kn = k0 + 32;
            #pragma unroll
            for (int j = 0; j < 2; j++) {
                int idx = tid + j * 256;
                int r = idx >> 3, c4 = idx & 7;
                raA[j] = *(const float4*)&A[(q0 + r) * LK + kn + c4 * 4];
            }
            #pragma unroll
            for (int j = 0; j < 2; j++) {
                int idx = tid + j * 256;
                int r = idx >> 4, c4 = idx & 15;
                raV[j] = *(const float4*)&V[(kn + r) * DV + d0 + c4 * 4];
            }
        }

        #pragma unroll
        for (int kk = 0; kk < 32; kk++) {
            float4 v = *(const float4*)&Vs[kk * PSB + tx * 4];
            u64 v0 = pack2(v.x, v.y);
            u64 v1 = pack2(v.z, v.w);
            float4 a = *(const float4*)&As[kk * PSB + ty * 4];
            u64 d0p = dup2(a.x), d1p = dup2(a.y), d2p = dup2(a.z), d3p = dup2(a.w);
            fma2(acc[0][0], d0p, v0); fma2(acc[0][1], d0p, v1);
            fma2(acc[1][0], d1p, v0); fma2(acc[1][1], d1p, v1);
            fma2(acc[2][0], d2p, v0); fma2(acc[2][1], d2p, v1);
            fma2(acc[3][0], d3p, v0); fma2(acc[3][1], d3p, v1);
        }
        __syncthreads();
    }

    #pragma unroll
    for (int i = 0; i < 4; i++) {
        float2 p0 = unpack2(acc[i][0]);
        float2 p1 = unpack2(acc[i][1]);
        *(float4*)&out[b * LQ * DV + (q0 + ty * 4 + i) * DV + d0 + tx * 4] =
            make_float4(p0.x, p0.y, p1.x, p1.y);
    }
}

extern "C" void kernel_launch(void* const* d_in, const int* in_sizes, int n_in,
                              void* d_out, int out_size) {
    const float* queries    = (const float*)d_in[0];
    const float* keyes      = (const float*)d_in[1];
    const float* values     = (const float*)d_in[2];
    const int*   valid_lens = (const int*)d_in[3];
    const float* W_q        = (const float*)d_in[4];
    const float* W_k        = (const float*)d_in[5];
    const float* W_v        = (const float*)d_in[6];
    float* out = (float*)d_out;

    proj_kernel<<<dim3(4, 16, 2), 256>>>(queries, W_q, keyes, W_k);
    scores_kernel<<<dim3(8, 8, 8), 256>>>(W_v, valid_lens);
    softmax_kernel<<<dim3(8, 8), 256>>>();
    out_kernel<<<dim3(4, 4, 8), 256>>>(values, out);
}

// round 3
// speedup vs baseline: 1.3723x; 1.3723x over previous
#include <cuda_runtime.h>

#define NB 8
#define LQ 256
#define LK 256
#define HH 256
#define DV 256
#define MASK_VALUE -1000000.0f

typedef unsigned long long u64;

// Scratch (allocation-free rule: device globals)
__device__ float g_Qp[NB * LQ * HH];
__device__ float g_Kp[NB * LK * HH];
__device__ float g_S[NB * LQ * LK];

__device__ __forceinline__ float tanh_fast(float x) {
    float y;
    asm("tanh.approx.f32 %0, %1;" : "=f"(y) : "f"(x));
    return y;
}

__device__ __forceinline__ u64 pack2(float lo, float hi) {
    u64 r;
    asm("mov.b64 %0, {%1, %2};" : "=l"(r) : "f"(lo), "f"(hi));
    return r;
}
__device__ __forceinline__ u64 dup2(float x) { return pack2(x, x); }

__device__ __forceinline__ void fma2(u64& d, u64 a, u64 b) {
    asm("fma.rn.f32x2 %0, %1, %2, %0;" : "+l"(d) : "l"(a), "l"(b));
}
__device__ __forceinline__ float2 unpack2(u64 v) {
    float2 f;
    asm("mov.b64 {%0, %1}, %2;" : "=f"(f.x), "=f"(f.y) : "l"(v));
    return f;
}

#define PSB 68  // smem row stride (floats) for B tiles [k][n]

// ---------------------------------------------------------------------------
// Projection NT GEMM: C[m][n] = sum_k X[m][k] * W[n][k]
// A (X) stays in registers (global loads, L1-broadcast across tx lanes).
// B (W) staged transposed into smem [k][n], double-buffered.
// Tile 64m x 64n, 256 threads, thread computes 4x4 via FFMA2.
// ---------------------------------------------------------------------------
__global__ void __launch_bounds__(256) proj_kernel(
    const float* __restrict__ Xq, const float* __restrict__ Wq,
    const float* __restrict__ Xk, const float* __restrict__ Wk) {
    const float* X;
    const float* W;
    float* C;
    if (blockIdx.z == 0) { X = Xq; W = Wq; C = g_Qp; }
    else                 { X = Xk; W = Wk; C = g_Kp; }

    __shared__ float Bs[2][32 * PSB];

    const int tid = threadIdx.x;
    const int tx = tid & 15;   // n: tx*4
    const int ty = tid >> 4;   // m: ty*4
    const int m0 = blockIdx.y * 64;
    const int n0 = blockIdx.x * 64;

    // staging indices: W tile is 64 n-rows x 32 k; 2 float4 per thread
    const int sr0 = tid >> 3;        // n-row 0..31
    const int sc4 = tid & 7;         // k-float4 0..7
    const float* Wp0 = W + (n0 + sr0) * 256 + sc4 * 4;
    const float* Wp1 = Wp0 + 32 * 256;

    u64 acc[4][2];
    #pragma unroll
    for (int i = 0; i < 4; i++) { acc[i][0] = 0ull; acc[i][1] = 0ull; }

    const float* Arow = X + (m0 + ty * 4) * 256;

    // prefetch W tile 0 and A chunk 0
    float4 w0 = *(const float4*)Wp0;
    float4 w1 = *(const float4*)Wp1;
    float4 abuf[2][4];
    #pragma unroll
    for (int i = 0; i < 4; i++)
        abuf[0][i] = *(const float4*)(Arow + i * 256);

    for (int t = 0; t < 8; t++) {
        float* B = Bs[t & 1];
        // transposed STS of the prefetched W tile
        B[(sc4 * 4 + 0) * PSB + sr0] = w0.x;
        B[(sc4 * 4 + 1) * PSB + sr0] = w0.y;
        B[(sc4 * 4 + 2) * PSB + sr0] = w0.z;
        B[(sc4 * 4 + 3) * PSB + sr0] = w0.w;
        B[(sc4 * 4 + 0) * PSB + sr0 + 32] = w1.x;
        B[(sc4 * 4 + 1) * PSB + sr0 + 32] = w1.y;
        B[(sc4 * 4 + 2) * PSB + sr0 + 32] = w1.z;
        B[(sc4 * 4 + 3) * PSB + sr0 + 32] = w1.w;
        __syncthreads();

        if (t < 7) {
            w0 = *(const float4*)(Wp0 + (t + 1) * 32);
            w1 = *(const float4*)(Wp1 + (t + 1) * 32);
        }

        const int kbase = t * 32;
        #pragma unroll
        for (int c = 0; c < 8; c++) {
            const int knext = kbase + c * 4 + 4;
            if (knext < 256) {
                #pragma unroll
                for (int i = 0; i < 4; i++)
                    abuf[(c + 1) & 1][i] = *(const float4*)(Arow + i * 256 + knext);
            }
            const float* ap = (const float*)abuf[c & 1];
            #pragma unroll
            for (int j = 0; j < 4; j++) {
                ulonglong2 b = *(const ulonglong2*)&B[(c * 4 + j) * PSB + tx * 4];
                u64 d0 = dup2(ap[0 * 4 + j]);
                u64 d1 = dup2(ap[1 * 4 + j]);
                u64 d2 = dup2(ap[2 * 4 + j]);
                u64 d3 = dup2(ap[3 * 4 + j]);
                fma2(acc[0][0], d0, b.x); fma2(acc[0][1], d0, b.y);
                fma2(acc[1][0], d1, b.x); fma2(acc[1][1], d1, b.y);
                fma2(acc[2][0], d2, b.x); fma2(acc[2][1], d2, b.y);
                fma2(acc[3][0], d3, b.x); fma2(acc[3][1], d3, b.y);
            }
        }
        // no trailing sync needed: double buffer + top-of-loop sync protects WAR
    }

    #pragma unroll
    for (int i = 0; i < 4; i++) {
        float2 p0 = unpack2(acc[i][0]);
        float2 p1 = unpack2(acc[i][1]);
        *(float4*)&C[(m0 + ty * 4 + i) * 256 + n0 + tx * 4] =
            make_float4(p0.x, p0.y, p1.x, p1.y);
    }
}

// ---------------------------------------------------------------------------
// Scores: S[b][q][k] = sum_h Wv[h] * tanh(Qp[b][q][h] + Kp[b][k][h]),
// masked to MASK_VALUE where k >= valid_len[b]. Fully-masked 32x32 tiles skip
// all compute. MUFU-bound by design (R1 version, measured near floor).
// ---------------------------------------------------------------------------
__global__ void scores_kernel(const float* __restrict__ Wv,
                              const int* __restrict__ vlens) {
    const int b = blockIdx.z;
    const int q0 = blockIdx.y * 32;
    const int k0 = blockIdx.x * 32;
    const int tid = threadIdx.x;
    const int tx = tid & 15;
    const int ty = tid >> 4;
    const int vl = vlens[b];
    float* S = g_S + b * LQ * LK;

    if (k0 >= vl) {
        const float2 mv = make_float2(MASK_VALUE, MASK_VALUE);
        #pragma unroll
        for (int i = 0; i < 2; i++)
            *(float2*)&S[(q0 + ty * 2 + i) * LK + k0 + tx * 2] = mv;
        return;
    }

    __shared__ float Qs[64][34];
    __shared__ float Ks[64][34];
    __shared__ float sWv[256];

    sWv[tid] = Wv[tid];

    const float* Qb = g_Qp + (b * LQ + q0) * HH;
    const float* Kb = g_Kp + (b * LK + k0) * HH;

    float a00 = 0.f, a01 = 0.f, a10 = 0.f, a11 = 0.f;

    for (int h0 = 0; h0 < HH; h0 += 64) {
        #pragma unroll
        for (int idx = tid; idx < 32 * 64; idx += 256) {
            int r = idx >> 6;
            int h = idx & 63;
            Qs[h][r] = Qb[r * HH + h0 + h];
            Ks[h][r] = Kb[r * HH + h0 + h];
        }
        __syncthreads();
        #pragma unroll 8
        for (int h = 0; h < 64; h++) {
            float2 qv = *(const float2*)&Qs[h][ty * 2];
            float2 kv = *(const float2*)&Ks[h][tx * 2];
            float wv = sWv[h0 + h];
            a00 += wv * tanh_fast(qv.x + kv.x);
            a01 += wv * tanh_fast(qv.x + kv.y);
            a10 += wv * tanh_fast(qv.y + kv.x);
            a11 += wv * tanh_fast(qv.y + kv.y);
        }
        __syncthreads();
    }

    const int kA = k0 + tx * 2;
    const int kB = kA + 1;
    const int qA = q0 + ty * 2;
    const int qB = qA + 1;
    S[qA * LK + kA] = (kA < vl) ? a00 : MASK_VALUE;
    S[qA * LK + kB] = (kB < vl) ? a01 : MASK_VALUE;
    S[qB * LK + kA] = (kA < vl) ? a10 : MASK_VALUE;
    S[qB * LK + kB] = (kB < vl) ? a11 : MASK_VALUE;
}

// ---------------------------------------------------------------------------
// Softmax over axis=1 (QUERY axis) per (b, k) column — reference quirk.
// ---------------------------------------------------------------------------
__global__ void softmax_kernel() {
    const int b = blockIdx.y;
    const int tx = threadIdx.x & 31;
    const int ty = threadIdx.x >> 5;  // 0..7
    const int k = blockIdx.x * 32 + tx;
    float* S = g_S + b * LQ * LK;

    float vals[32];
    float m = -3.4e38f;
    #pragma unroll
    for (int i = 0; i < 32; i++) {
        vals[i] = S[(i * 8 + ty) * LK + k];
        m = fmaxf(m, vals[i]);
    }

    __shared__ float red[8][33];
    red[ty][tx] = m;
    __syncthreads();
    float M = red[0][tx];
    #pragma unroll
    for (int t = 1; t < 8; t++) M = fmaxf(M, red[t][tx]);
    __syncthreads();

    float s = 0.f;
    #pragma unroll
    for (int i = 0; i < 32; i++) {
        vals[i] = __expf(vals[i] - M);
        s += vals[i];
    }
    red[ty][tx] = s;
    __syncthreads();
    float SUM = 0.f;
    #pragma unroll
    for (int t = 0; t < 8; t++) SUM += red[t][tx];

    const float inv = 1.0f / SUM;
    #pragma unroll
    for (int i = 0; i < 32; i++)
        S[(i * 8 + ty) * LK + k] = vals[i] * inv;
}

// ---------------------------------------------------------------------------
// Output NN GEMM: out[b][q][d] = sum_k Attn[b][q][k] * V[b][k][d]
// A (attn) in registers from global; B (V) staged direct (no transpose),
// double-buffered. Tile 64q x 64d, 256 threads, 4x4 per thread via FFMA2.
// ---------------------------------------------------------------------------
__global__ void __launch_bounds__(256) out_kernel(
    const float* __restrict__ Vv, float* __restrict__ out) {
    const int b = blockIdx.z;
    const int q0 = blockIdx.y * 64;
    const int d0 = blockIdx.x * 64;
    const int tid = threadIdx.x;
    const int tx = tid & 15;   // d: tx*4
    const int ty = tid >> 4;   // q: ty*4

    const float* A = g_S + b * LQ * LK;
    const float* V = Vv + b * LK * DV;

    __shared__ float Bs[2][32 * PSB];

    // staging: V tile 32k x 64d, direct float4 stores
    const int sr0 = tid >> 4;       // k-row 0..15
    const int sc4 = tid & 15;       // d-float4 0..15
    const float* Vp0 = V + sr0 * 256 + d0 + sc4 * 4;
    const float* Vp1 = Vp0 + 16 * 256;

    u64 acc[4][2];
    #pragma unroll
    for (int i = 0; i < 4; i++) { acc[i][0] = 0ull; acc[i][1] = 0ull; }

    const float* Arow = A + (q0 + ty * 4) * LK;

    float4 v0 = *(const float4*)Vp0;
    float4 v1 = *(const float4*)Vp1;
    float4 abuf[2][4];
    #pragma unroll
    for (int i = 0; i < 4; i++)
        abuf[0][i] = *(const float4*)(Arow + i * 256);

    for (int t = 0; t < 8; t++) {
        float* B = Bs[t & 1];
        *(float4*)&B[sr0 * PSB + sc4 * 4] = v0;
        *(float4*)&B[(sr0 + 16) * PSB + sc4 * 4] = v1;
        __syncthreads();

        if (t < 7) {
            v0 = *(const float4*)(Vp0 + (t + 1) * 32 * 256);
            v1 = *(const float4*)(Vp1 + (t + 1) * 32 * 256);
        }

        const int kbase = t * 32;
        #pragma unroll
        for (int c = 0; c < 8; c++) {
            const int knext = kbase + c * 4 + 4;
            if (knext < 256) {
                #pragma unroll
                for (int i = 0; i < 4; i++)
                    abuf[(c + 1) & 1][i] = *(const float4*)(Arow + i * 256 + knext);
            }
            const float* ap = (const float*)abuf[c & 1];
            #pragma unroll
            for (int j = 0; j < 4; j++) {
                ulonglong2 bb = *(const ulonglong2*)&B[(c * 4 + j) * PSB + tx * 4];
                u64 d0p = dup2(ap[0 * 4 + j]);
                u64 d1p = dup2(ap[1 * 4 + j]);
                u64 d2p = dup2(ap[2 * 4 + j]);
                u64 d3p = dup2(ap[3 * 4 + j]);
                fma2(acc[0][0], d0p, bb.x); fma2(acc[0][1], d0p, bb.y);
                fma2(acc[1][0], d1p, bb.x); fma2(acc[1][1], d1p, bb.y);
                fma2(acc[2][0], d2p, bb.x); fma2(acc[2][1], d2p, bb.y);
                fma2(acc[3][0], d3p, bb.x); fma2(acc[3][1], d3p, bb.y);
            }
        }
    }

    #pragma unroll
    for (int i = 0; i < 4; i++) {
        float2 p0 = unpack2(acc[i][0]);
        float2 p1 = unpack2(acc[i][1]);
        *(float4*)&out[b * LQ * DV + (q0 + ty * 4 + i) * DV + d0 + tx * 4] =
            make_float4(p0.x, p0.y, p1.x, p1.y);
    }
}

extern "C" void kernel_launch(void* const* d_in, const int* in_sizes, int n_in,
                              void* d_out, int out_size) {
    const float* queries    = (const float*)d_in[0];
    const float* keyes      = (const float*)d_in[1];
    const float* values     = (const float*)d_in[2];
    const int*   valid_lens = (const int*)d_in[3];
    const float* W_q        = (const float*)d_in[4];
    const float* W_k        = (const float*)d_in[5];
    const float* W_v        = (const float*)d_in[6];
    float* out = (float*)d_out;

    proj_kernel<<<dim3(4, 32, 2), 256>>>(queries, W_q, keyes, W_k);
    scores_kernel<<<dim3(8, 8, 8), 256>>>(W_v, valid_lens);
    softmax_kernel<<<dim3(8, 8), 256>>>();
    out_kernel<<<dim3(4, 4, 8), 256>>>(values, out);
}

// round 4
// speedup vs baseline: 1.4078x; 1.0259x over previous
#include <cuda_runtime.h>

#define NB 8
#define LQ 256
#define LK 256
#define HH 256
#define DV 256
#define MASK_VALUE -1000000.0f

typedef unsigned long long u64;

// Scratch (allocation-free rule: device globals)
__device__ float g_Qp[NB * LQ * HH];
__device__ float g_Kp[NB * LK * HH];
__device__ float g_S[NB * LQ * LK];

__device__ __forceinline__ float tanh_fast(float x) {
    float y;
    asm("tanh.approx.f32 %0, %1;" : "=f"(y) : "f"(x));
    return y;
}

__device__ __forceinline__ u64 pack2(float lo, float hi) {
    u64 r;
    asm("mov.b64 %0, {%1, %2};" : "=l"(r) : "f"(lo), "f"(hi));
    return r;
}
__device__ __forceinline__ u64 dup2(float x) { return pack2(x, x); }

__device__ __forceinline__ void fma2(u64& d, u64 a, u64 b) {
    asm("fma.rn.f32x2 %0, %1, %2, %0;" : "+l"(d) : "l"(a), "l"(b));
}
__device__ __forceinline__ float2 unpack2(u64 v) {
    float2 f;
    asm("mov.b64 {%0, %1}, %2;" : "=f"(f.x), "=f"(f.y) : "l"(v));
    return f;
}

#define PS 36  // smem row stride (floats) for 32-wide B tiles [k][n]

// ---------------------------------------------------------------------------
// Projection NT GEMM: C[m][n] = sum_k X[m][k] * W[n][k]
// 32m x 32n tiles, 64 threads (4x4 per thread), grid (8,64,2) = 1024 blocks.
// A in registers (L1-broadcast LDG), B transposed in smem, double-buffered.
// ---------------------------------------------------------------------------
__global__ void __launch_bounds__(64) proj_kernel(
    const float* __restrict__ Xq, const float* __restrict__ Wq,
    const float* __restrict__ Xk, const float* __restrict__ Wk) {
    const float* X;
    const float* W;
    float* C;
    if (blockIdx.z == 0) { X = Xq; W = Wq; C = g_Qp; }
    else                 { X = Xk; W = Wk; C = g_Kp; }

    __shared__ float Bs[2][32 * PS];

    const int tid = threadIdx.x;
    const int tx = tid & 7;    // n: tx*4
    const int ty = tid >> 3;   // m: ty*4
    const int m0 = blockIdx.y * 32;
    const int n0 = blockIdx.x * 32;

    // staging: W tile 32 n-rows x 32 k -> 4 float4 per thread
    const int sr = tid >> 1;          // n-row 0..31
    const int sb = (tid & 1) * 4;     // k-float4 base: 0 or 4
    const float* Wp = W + (n0 + sr) * 256 + sb * 4;

    u64 acc[4][2];
    #pragma unroll
    for (int i = 0; i < 4; i++) { acc[i][0] = 0ull; acc[i][1] = 0ull; }

    const float* Arow = X + (m0 + ty * 4) * 256;

    // prefetch W tile 0 and A group 0
    float4 w[4];
    #pragma unroll
    for (int j = 0; j < 4; j++) w[j] = *(const float4*)(Wp + j * 4);
    float4 abuf[2][4];
    #pragma unroll
    for (int i = 0; i < 4; i++)
        abuf[0][i] = *(const float4*)(Arow + i * 256);

    for (int t = 0; t < 8; t++) {
        float* B = Bs[t & 1];
        #pragma unroll
        for (int j = 0; j < 4; j++) {
            int c = (sb + j) * 4;
            B[(c + 0) * PS + sr] = w[j].x;
            B[(c + 1) * PS + sr] = w[j].y;
            B[(c + 2) * PS + sr] = w[j].z;
            B[(c + 3) * PS + sr] = w[j].w;
        }
        __syncthreads();

        if (t < 7) {
            #pragma unroll
            for (int j = 0; j < 4; j++)
                w[j] = *(const float4*)(Wp + (t + 1) * 32 + j * 4);
        }

        const int kbase = t * 32;
        #pragma unroll
        for (int c = 0; c < 8; c++) {
            const int knext = kbase + c * 4 + 4;
            if (knext < 256) {
                #pragma unroll
                for (int i = 0; i < 4; i++)
                    abuf[(c + 1) & 1][i] = *(const float4*)(Arow + i * 256 + knext);
            }
            const float* ap = (const float*)abuf[c & 1];
            #pragma unroll
            for (int j = 0; j < 4; j++) {
                ulonglong2 b = *(const ulonglong2*)&B[(c * 4 + j) * PS + tx * 4];
                u64 d0 = dup2(ap[0 * 4 + j]);
                u64 d1 = dup2(ap[1 * 4 + j]);
                u64 d2 = dup2(ap[2 * 4 + j]);
                u64 d3 = dup2(ap[3 * 4 + j]);
                fma2(acc[0][0], d0, b.x); fma2(acc[0][1], d0, b.y);
                fma2(acc[1][0], d1, b.x); fma2(acc[1][1], d1, b.y);
                fma2(acc[2][0], d2, b.x); fma2(acc[2][1], d2, b.y);
                fma2(acc[3][0], d3, b.x); fma2(acc[3][1], d3, b.y);
            }
        }
    }

    #pragma unroll
    for (int i = 0; i < 4; i++) {
        float2 p0 = unpack2(acc[i][0]);
        float2 p1 = unpack2(acc[i][1]);
        *(float4*)&C[(m0 + ty * 4 + i) * 256 + n0 + tx * 4] =
            make_float4(p0.x, p0.y, p1.x, p1.y);
    }
}

// ---------------------------------------------------------------------------
// Scores: S[b][q][k] = sum_h Wv[h] * tanh(Qp[b][q][h] + Kp[b][k][h]),
// masked to MASK_VALUE where k >= valid_len[b]. Fully-masked 32x32 tiles skip
// all compute. MUFU-bound by design.
// ---------------------------------------------------------------------------
__global__ void scores_kernel(const float* __restrict__ Wv,
                              const int* __restrict__ vlens) {
    const int b = blockIdx.z;
    const int q0 = blockIdx.y * 32;
    const int k0 = blockIdx.x * 32;
    const int tid = threadIdx.x;
    const int tx = tid & 15;
    const int ty = tid >> 4;
    const int vl = vlens[b];
    float* S = g_S + b * LQ * LK;

    if (k0 >= vl) {
        const float2 mv = make_float2(MASK_VALUE, MASK_VALUE);
        #pragma unroll
        for (int i = 0; i < 2; i++)
            *(float2*)&S[(q0 + ty * 2 + i) * LK + k0 + tx * 2] = mv;
        return;
    }

    __shared__ float Qs[64][34];
    __shared__ float Ks[64][34];
    __shared__ float sWv[256];

    sWv[tid] = Wv[tid];

    const float* Qb = g_Qp + (b * LQ + q0) * HH;
    const float* Kb = g_Kp + (b * LK + k0) * HH;

    float a00 = 0.f, a01 = 0.f, a10 = 0.f, a11 = 0.f;

    for (int h0 = 0; h0 < HH; h0 += 64) {
        #pragma unroll
        for (int idx = tid; idx < 32 * 64; idx += 256) {
            int r = idx >> 6;
            int h = idx & 63;
            Qs[h][r] = Qb[r * HH + h0 + h];
            Ks[h][r] = Kb[r * HH + h0 + h];
        }
        __syncthreads();
        #pragma unroll 8
        for (int h = 0; h < 64; h++) {
            float2 qv = *(const float2*)&Qs[h][ty * 2];
            float2 kv = *(const float2*)&Ks[h][tx * 2];
            float wv = sWv[h0 + h];
            a00 += wv * tanh_fast(qv.x + kv.x);
            a01 += wv * tanh_fast(qv.x + kv.y);
            a10 += wv * tanh_fast(qv.y + kv.x);
            a11 += wv * tanh_fast(qv.y + kv.y);
        }
        __syncthreads();
    }

    const int kA = k0 + tx * 2;
    const int kB = kA + 1;
    const int qA = q0 + ty * 2;
    const int qB = qA + 1;
    S[qA * LK + kA] = (kA < vl) ? a00 : MASK_VALUE;
    S[qA * LK + kB] = (kB < vl) ? a01 : MASK_VALUE;
    S[qB * LK + kA] = (kA < vl) ? a10 : MASK_VALUE;
    S[qB * LK + kB] = (kB < vl) ? a11 : MASK_VALUE;
}

// ---------------------------------------------------------------------------
// Softmax over axis=1 (QUERY axis) per (b, k) column — reference quirk.
// ---------------------------------------------------------------------------
__global__ void softmax_kernel() {
    const int b = blockIdx.y;
    const int tx = threadIdx.x & 31;
    const int ty = threadIdx.x >> 5;  // 0..7
    const int k = blockIdx.x * 32 + tx;
    float* S = g_S + b * LQ * LK;

    float vals[32];
    float m = -3.4e38f;
    #pragma unroll
    for (int i = 0; i < 32; i++) {
        vals[i] = S[(i * 8 + ty) * LK + k];
        m = fmaxf(m, vals[i]);
    }

    __shared__ float red[8][33];
    red[ty][tx] = m;
    __syncthreads();
    float M = red[0][tx];
    #pragma unroll
    for (int t = 1; t < 8; t++) M = fmaxf(M, red[t][tx]);
    __syncthreads();

    float s = 0.f;
    #pragma unroll
    for (int i = 0; i < 32; i++) {
        vals[i] = __expf(vals[i] - M);
        s += vals[i];
    }
    red[ty][tx] = s;
    __syncthreads();
    float SUM = 0.f;
    #pragma unroll
    for (int t = 0; t < 8; t++) SUM += red[t][tx];

    const float inv = 1.0f / SUM;
    #pragma unroll
    for (int i = 0; i < 32; i++)
        S[(i * 8 + ty) * LK + k] = vals[i] * inv;
}

// ---------------------------------------------------------------------------
// Output NN GEMM: out[b][q][d] = sum_k Attn[b][q][k] * V[b][k][d]
// 32q x 32d tiles, 64 threads (4x4 per thread), grid (8,8,8) = 512 blocks.
// A (attn) in registers; V staged direct into smem, double-buffered.
// ---------------------------------------------------------------------------
__global__ void __launch_bounds__(64) out_kernel(
    const float* __restrict__ Vv, float* __restrict__ out) {
    const int b = blockIdx.z;
    const int q0 = blockIdx.y * 32;
    const int d0 = blockIdx.x * 32;
    const int tid = threadIdx.x;
    const int tx = tid & 7;    // d: tx*4
    const int ty = tid >> 3;   // q: ty*4

    const float* A = g_S + b * LQ * LK;
    const float* V = Vv + b * LK * DV;

    __shared__ float Bs[2][32 * PS];

    // staging: V tile 32k x 32d -> 4 float4 per thread, direct (no transpose)
    const int sr = tid >> 1;          // k-row 0..31
    const int sb = (tid & 1) * 4;     // d-float4 base: 0 or 4
    const float* Vp = V + sr * 256 + d0 + sb * 4;

    u64 acc[4][2];
    #pragma unroll
    for (int i = 0; i < 4; i++) { acc[i][0] = 0ull; acc[i][1] = 0ull; }

    const float* Arow = A + (q0 + ty * 4) * LK;

    float4 v[4];
    #pragma unroll
    for (int j = 0; j < 4; j++) v[j] = *(const float4*)(Vp + j * 4);
    float4 abuf[2][4];
    #pragma unroll
    for (int i = 0; i < 4; i++)
        abuf[0][i] = *(const float4*)(Arow + i * 256);

    for (int t = 0; t < 8; t++) {
        float* B = Bs[t & 1];
        #pragma unroll
        for (int j = 0; j < 4; j++)
            *(float4*)&B[sr * PS + (sb + j) * 4] = v[j];
        __syncthreads();

        if (t < 7) {
            #pragma unroll
            for (int j = 0; j < 4; j++)
                v[j] = *(const float4*)(Vp + (t + 1) * 32 * 256 + j * 4);
        }

        const int kbase = t * 32;
        #pragma unroll
        for (int c = 0; c < 8; c++) {
            const int knext = kbase + c * 4 + 4;
            if (knext < 256) {
                #pragma unroll
                for (int i = 0; i < 4; i++)
                    abuf[(c + 1) & 1][i] = *(const float4*)(Arow + i * 256 + knext);
            }
            const float* ap = (const float*)abuf[c & 1];
            #pragma unroll
            for (int j = 0; j < 4; j++) {
                ulonglong2 bb = *(const ulonglong2*)&B[(c * 4 + j) * PS + tx * 4];
                u64 d0p = dup2(ap[0 * 4 + j]);
                u64 d1p = dup2(ap[1 * 4 + j]);
                u64 d2p = dup2(ap[2 * 4 + j]);
                u64 d3p = dup2(ap[3 * 4 + j]);
                fma2(acc[0][0], d0p, bb.x); fma2(acc[0][1], d0p, bb.y);
                fma2(acc[1][0], d1p, bb.x); fma2(acc[1][1], d1p, bb.y);
                fma2(acc[2][0], d2p, bb.x); fma2(acc[2][1], d2p, bb.y);
                fma2(acc[3][0], d3p, bb.x); fma2(acc[3][1], d3p, bb.y);
            }
        }
    }

    #pragma unroll
    for (int i = 0; i < 4; i++) {
        float2 p0 = unpack2(acc[i][0]);
        float2 p1 = unpack2(acc[i][1]);
        *(float4*)&out[b * LQ * DV + (q0 + ty * 4 + i) * DV + d0 + tx * 4] =
            make_float4(p0.x, p0.y, p1.x, p1.y);
    }
}

extern "C" void kernel_launch(void* const* d_in, const int* in_sizes, int n_in,
                              void* d_out, int out_size) {
    const float* queries    = (const float*)d_in[0];
    const float* keyes      = (const float*)d_in[1];
    const float* values     = (const float*)d_in[2];
    const int*   valid_lens = (const int*)d_in[3];
    const float* W_q        = (const float*)d_in[4];
    const float* W_k        = (const float*)d_in[5];
    const float* W_v        = (const float*)d_in[6];
    float* out = (float*)d_out;

    proj_kernel<<<dim3(8, 64, 2), 64>>>(queries, W_q, keyes, W_k);
    scores_kernel<<<dim3(8, 8, 8), 256>>>(W_v, valid_lens);
    softmax_kernel<<<dim3(8, 8), 256>>>();
    out_kernel<<<dim3(8, 8, 8), 64>>>(values, out);
}

// round 5
// speedup vs baseline: 1.8813x; 1.3363x over previous
#include <cuda_runtime.h>
#include <cstdint>

#define NB 8
#define LQ 256
#define LK 256
#define HH 256
#define DV 256
#define MASK_VALUE -1000000.0f

// Scratch (allocation-free rule: device globals)
__device__ float g_Qp[NB * LQ * HH];
__device__ float g_Kp[NB * LK * HH];
__device__ float g_S[NB * LQ * LK];

__device__ __forceinline__ float tanh_fast(float x) {
    float y;
    asm("tanh.approx.f32 %0, %1;" : "=f"(y) : "f"(x));
    return y;
}

__device__ __forceinline__ uint32_t f2tf(float x) {
    uint32_t r;
    asm("cvt.rna.tf32.f32 %0, %1;" : "=r"(r) : "f"(x));
    return r;
}

// D += A(16x8,row) * B(8x8,col)  in tf32, fp32 accum
__device__ __forceinline__ void mma8(float* d, const uint32_t* a, const uint32_t* b) {
    asm("mma.sync.aligned.m16n8k8.row.col.f32.tf32.tf32.f32 "
        "{%0,%1,%2,%3}, {%4,%5,%6,%7}, {%8,%9}, {%0,%1,%2,%3};"
        : "+f"(d[0]), "+f"(d[1]), "+f"(d[2]), "+f"(d[3])
        : "r"(a[0]), "r"(a[1]), "r"(a[2]), "r"(a[3]), "r"(b[0]), "r"(b[1]));
}

#define TS 36  // smem stride for k-contiguous tiles: fragment LDS conflict-free
#define VS 35  // smem stride for transposed V tile: 2-way worst case

// ---------------------------------------------------------------------------
// Projection NT GEMM (tf32 tensor cores): C[m][n] = sum_k X[m][k]*W[n][k]
// CTA 64m x 64n, 4 warps (2x2) of 32x32 warp tiles; kc=32, double-buffered.
// z=0: queries@W_q^T -> g_Qp ; z=1: keyes@W_k^T -> g_Kp
// ---------------------------------------------------------------------------
__global__ void __launch_bounds__(128) proj_kernel(
    const float* __restrict__ Xq, const float* __restrict__ Wq,
    const float* __restrict__ Xk, const float* __restrict__ Wk) {
    const float* X;
    const float* W;
    float* C;
    if (blockIdx.z == 0) { X = Xq; W = Wq; C = g_Qp; }
    else                 { X = Xk; W = Wk; C = g_Kp; }

    __shared__ uint32_t Xs[2][64 * TS];
    __shared__ uint32_t Ws[2][64 * TS];

    const int tid = threadIdx.x;
    const int lane = tid & 31;
    const int warp = tid >> 5;
    const int gid = lane >> 2;   // 0..7
    const int tig = lane & 3;    // 0..3
    const int wm = (warp & 1) * 32;
    const int wn = (warp >> 1) * 32;
    const int m0 = blockIdx.y * 64;
    const int n0 = blockIdx.x * 64;

    int srow[4], sc4[4];
    #pragma unroll
    for (int j = 0; j < 4; j++) {
        int idx = tid + j * 128;
        srow[j] = idx >> 3;   // 0..63
        sc4[j]  = idx & 7;    // 0..7
    }

    float d[2][4][4];
    #pragma unroll
    for (int i = 0; i < 2; i++)
        #pragma unroll
        for (int j = 0; j < 4; j++)
            #pragma unroll
            for (int e = 0; e < 4; e++) d[i][j][e] = 0.f;

    float4 xv[4], wv[4];
    #pragma unroll
    for (int j = 0; j < 4; j++) {
        xv[j] = *(const float4*)&X[(m0 + srow[j]) * 256 + sc4[j] * 4];
        wv[j] = *(const float4*)&W[(n0 + srow[j]) * 256 + sc4[j] * 4];
    }

    for (int c = 0; c < 8; c++) {
        uint32_t* XB = Xs[c & 1];
        uint32_t* WB = Ws[c & 1];
        #pragma unroll
        for (int j = 0; j < 4; j++) {
            uint32_t* px = &XB[srow[j] * TS + sc4[j] * 4];
            px[0] = f2tf(xv[j].x); px[1] = f2tf(xv[j].y);
            px[2] = f2tf(xv[j].z); px[3] = f2tf(xv[j].w);
            uint32_t* pw = &WB[srow[j] * TS + sc4[j] * 4];
            pw[0] = f2tf(wv[j].x); pw[1] = f2tf(wv[j].y);
            pw[2] = f2tf(wv[j].z); pw[3] = f2tf(wv[j].w);
        }
        __syncthreads();

        if (c < 7) {
            const int k0 = (c + 1) * 32;
            #pragma unroll
            for (int j = 0; j < 4; j++) {
                xv[j] = *(const float4*)&X[(m0 + srow[j]) * 256 + k0 + sc4[j] * 4];
                wv[j] = *(const float4*)&W[(n0 + srow[j]) * 256 + k0 + sc4[j] * 4];
            }
        }

        #pragma unroll
        for (int ks = 0; ks < 4; ks++) {
            const int kk = ks * 8;
            uint32_t a[2][4], b[4][2];
            #pragma unroll
            for (int i = 0; i < 2; i++) {
                int r = wm + i * 16 + gid;
                a[i][0] = XB[r * TS + kk + tig];
                a[i][1] = XB[(r + 8) * TS + kk + tig];
                a[i][2] = XB[r * TS + kk + tig + 4];
                a[i][3] = XB[(r + 8) * TS + kk + tig + 4];
            }
            #pragma unroll
            for (int jn = 0; jn < 4; jn++) {
                int n = wn + jn * 8 + gid;
                b[jn][0] = WB[n * TS + kk + tig];
                b[jn][1] = WB[n * TS + kk + tig + 4];
            }
            #pragma unroll
            for (int i = 0; i < 2; i++)
                #pragma unroll
                for (int jn = 0; jn < 4; jn++) mma8(d[i][jn], a[i], b[jn]);
        }
    }

    #pragma unroll
    for (int i = 0; i < 2; i++)
        #pragma unroll
        for (int jn = 0; jn < 4; jn++) {
            int row = m0 + wm + i * 16 + gid;
            int col = n0 + wn + jn * 8 + tig * 2;
            *(float2*)&C[row * 256 + col] = make_float2(d[i][jn][0], d[i][jn][1]);
            *(float2*)&C[(row + 8) * 256 + col] = make_float2(d[i][jn][2], d[i][jn][3]);
        }
}

// ---------------------------------------------------------------------------
// Scores: S[b][q][k] = sum_h Wv[h] * tanh(Qp[b][q][h] + Kp[b][k][h]),
// masked to MASK_VALUE where k >= valid_len[b]. Fully-masked 32x32 tiles skip
// all compute. MUFU-bound by design.
// ---------------------------------------------------------------------------
__global__ void scores_kernel(const float* __restrict__ Wv,
                              const int* __restrict__ vlens) {
    const int b = blockIdx.z;
    const int q0 = blockIdx.y * 32;
    const int k0 = blockIdx.x * 32;
    const int tid = threadIdx.x;
    const int tx = tid & 15;
    const int ty = tid >> 4;
    const int vl = vlens[b];
    float* S = g_S + b * LQ * LK;

    if (k0 >= vl) {
        const float2 mv = make_float2(MASK_VALUE, MASK_VALUE);
        #pragma unroll
        for (int i = 0; i < 2; i++)
            *(float2*)&S[(q0 + ty * 2 + i) * LK + k0 + tx * 2] = mv;
        return;
    }

    __shared__ float Qs[64][34];
    __shared__ float Ks[64][34];
    __shared__ float sWv[256];

    sWv[tid] = Wv[tid];

    const float* Qb = g_Qp + (b * LQ + q0) * HH;
    const float* Kb = g_Kp + (b * LK + k0) * HH;

    float a00 = 0.f, a01 = 0.f, a10 = 0.f, a11 = 0.f;

    for (int h0 = 0; h0 < HH; h0 += 64) {
        #pragma unroll
        for (int idx = tid; idx < 32 * 64; idx += 256) {
            int r = idx >> 6;
            int h = idx & 63;
            Qs[h][r] = Qb[r * HH + h0 + h];
            Ks[h][r] = Kb[r * HH + h0 + h];
        }
        __syncthreads();
        #pragma unroll 8
        for (int h = 0; h < 64; h++) {
            float2 qv = *(const float2*)&Qs[h][ty * 2];
            float2 kv = *(const float2*)&Ks[h][tx * 2];
            float wv = sWv[h0 + h];
            a00 += wv * tanh_fast(qv.x + kv.x);
            a01 += wv * tanh_fast(qv.x + kv.y);
            a10 += wv * tanh_fast(qv.y + kv.x);
            a11 += wv * tanh_fast(qv.y + kv.y);
        }
        __syncthreads();
    }

    const int kA = k0 + tx * 2;
    const int kB = kA + 1;
    const int qA = q0 + ty * 2;
    const int qB = qA + 1;
    S[qA * LK + kA] = (kA < vl) ? a00 : MASK_VALUE;
    S[qA * LK + kB] = (kB < vl) ? a01 : MASK_VALUE;
    S[qB * LK + kA] = (kA < vl) ? a10 : MASK_VALUE;
    S[qB * LK + kB] = (kB < vl) ? a11 : MASK_VALUE;
}

// ---------------------------------------------------------------------------
// Softmax over axis=1 (QUERY axis) per (b, k) column — reference quirk.
// ---------------------------------------------------------------------------
__global__ void softmax_kernel() {
    const int b = blockIdx.y;
    const int tx = threadIdx.x & 31;
    const int ty = threadIdx.x >> 5;  // 0..7
    const int k = blockIdx.x * 32 + tx;
    float* S = g_S + b * LQ * LK;

    float vals[32];
    float m = -3.4e38f;
    #pragma unroll
    for (int i = 0; i < 32; i++) {
        vals[i] = S[(i * 8 + ty) * LK + k];
        m = fmaxf(m, vals[i]);
    }

    __shared__ float red[8][33];
    red[ty][tx] = m;
    __syncthreads();
    float M = red[0][tx];
    #pragma unroll
    for (int t = 1; t < 8; t++) M = fmaxf(M, red[t][tx]);
    __syncthreads();

    float s = 0.f;
    #pragma unroll
    for (int i = 0; i < 32; i++) {
        vals[i] = __expf(vals[i] - M);
        s += vals[i];
    }
    red[ty][tx] = s;
    __syncthreads();
    float SUM = 0.f;
    #pragma unroll
    for (int t = 0; t < 8; t++) SUM += red[t][tx];

    const float inv = 1.0f / SUM;
    #pragma unroll
    for (int i = 0; i < 32; i++)
        S[(i * 8 + ty) * LK + k] = vals[i] * inv;
}

// ---------------------------------------------------------------------------
// Output NN GEMM (tf32 tensor cores): out[b][q][d] = sum_k A[b][q][k]*V[b][k][d]
// A staged k-contiguous [q][36]; V staged TRANSPOSED [d][35] (mma needs B as
// [n][k]). CTA 64q x 64d, 4 warps of 32x32; kc=32, double-buffered.
// ---------------------------------------------------------------------------
__global__ void __launch_bounds__(128) out_kernel(
    const float* __restrict__ Vv, float* __restrict__ out) {
    const int b = blockIdx.z;
    const int q0 = blockIdx.y * 64;
    const int d0 = blockIdx.x * 64;
    const int tid = threadIdx.x;
    const int lane = tid & 31;
    const int warp = tid >> 5;
    const int gid = lane >> 2;
    const int tig = lane & 3;
    const int wq = (warp & 1) * 32;
    const int wn = (warp >> 1) * 32;

    const float* A = g_S + b * LQ * LK;
    const float* V = Vv + b * LK * DV;

    __shared__ uint32_t As[2][64 * TS];
    __shared__ uint32_t Vs[2][64 * VS];

    // A staging coords (64 q-rows x 32 k, float4)
    int arow[4], ac4[4];
    // V staging coords (32 k-rows x 64 d, float4) -> transposed store
    int vkr[4], vc4[4];
    #pragma unroll
    for (int j = 0; j < 4; j++) {
        int idx = tid + j * 128;
        arow[j] = idx >> 3;  ac4[j] = idx & 7;
        vkr[j]  = idx >> 4;  vc4[j] = idx & 15;
    }

    float d[2][4][4];
    #pragma unroll
    for (int i = 0; i < 2; i++)
        #pragma unroll
        for (int j = 0; j < 4; j++)
            #pragma unroll
            for (int e = 0; e < 4; e++) d[i][j][e] = 0.f;

    float4 av[4], vv[4];
    #pragma unroll
    for (int j = 0; j < 4; j++) {
        av[j] = *(const float4*)&A[(q0 + arow[j]) * LK + ac4[j] * 4];
        vv[j] = *(const float4*)&V[vkr[j] * DV + d0 + vc4[j] * 4];
    }

    for (int c = 0; c < 8; c++) {
        uint32_t* AB = As[c & 1];
        uint32_t* VB = Vs[c & 1];
        #pragma unroll
        for (int j = 0; j < 4; j++) {
            uint32_t* pa = &AB[arow[j] * TS + ac4[j] * 4];
            pa[0] = f2tf(av[j].x); pa[1] = f2tf(av[j].y);
            pa[2] = f2tf(av[j].z); pa[3] = f2tf(av[j].w);
            // transposed store of V: Vs[d][k]
            const int dc = vc4[j] * 4;
            VB[(dc + 0) * VS + vkr[j]] = f2tf(vv[j].x);
            VB[(dc + 1) * VS + vkr[j]] = f2tf(vv[j].y);
            VB[(dc + 2) * VS + vkr[j]] = f2tf(vv[j].z);
            VB[(dc + 3) * VS + vkr[j]] = f2tf(vv[j].w);
        }
        __syncthreads();

        if (c < 7) {
            const int k0 = (c + 1) * 32;
            #pragma unroll
            for (int j = 0; j < 4; j++) {
                av[j] = *(const float4*)&A[(q0 + arow[j]) * LK + k0 + ac4[j] * 4];
                vv[j] = *(const float4*)&V[(k0 + vkr[j]) * DV + d0 + vc4[j] * 4];
            }
        }

        #pragma unroll
        for (int ks = 0; ks < 4; ks++) {
            const int kk = ks * 8;
            uint32_t a[2][4], bfr[4][2];
            #pragma unroll
            for (int i = 0; i < 2; i++) {
                int r = wq + i * 16 + gid;
                a[i][0] = AB[r * TS + kk + tig];
                a[i][1] = AB[(r + 8) * TS + kk + tig];
                a[i][2] = AB[r * TS + kk + tig + 4];
                a[i][3] = AB[(r + 8) * TS + kk + tig + 4];
            }
            #pragma unroll
            for (int jn = 0; jn < 4; jn++) {
                int n = wn + jn * 8 + gid;
                bfr[jn][0] = VB[n * VS + kk + tig];
                bfr[jn][1] = VB[n * VS + kk + tig + 4];
            }
            #pragma unroll
            for (int i = 0; i < 2; i++)
                #pragma unroll
                for (int jn = 0; jn < 4; jn++) mma8(d[i][jn], a[i], bfr[jn]);
        }
    }

    float* O = out + b * LQ * DV;
    #pragma unroll
    for (int i = 0; i < 2; i++)
        #pragma unroll
        for (int jn = 0; jn < 4; jn++) {
            int row = q0 + wq + i * 16 + gid;
            int col = d0 + wn + jn * 8 + tig * 2;
            *(float2*)&O[row * DV + col] = make_float2(d[i][jn][0], d[i][jn][1]);
            *(float2*)&O[(row + 8) * DV + col] = make_float2(d[i][jn][2], d[i][jn][3]);
        }
}

extern "C" void kernel_launch(void* const* d_in, const int* in_sizes, int n_in,
                              void* d_out, int out_size) {
    const float* queries    = (const float*)d_in[0];
    const float* keyes      = (const float*)d_in[1];
    const float* values     = (const float*)d_in[2];
    const int*   valid_lens = (const int*)d_in[3];
    const float* W_q        = (const float*)d_in[4];
    const float* W_k        = (const float*)d_in[5];
    const float* W_v        = (const float*)d_in[6];
    float* out = (float*)d_out;

    proj_kernel<<<dim3(4, 32, 2), 128>>>(queries, W_q, keyes, W_k);
    scores_kernel<<<dim3(8, 8, 8), 256>>>(W_v, valid_lens);
    softmax_kernel<<<dim3(8, 8), 256>>>();
    out_kernel<<<dim3(4, 4, 8), 128>>>(values, out);
}